// round 10
// baseline (speedup 1.0000x reference)
#include <cuda_runtime.h>
#include <cstdint>

#define VS 100
#define BATCH 8
#define NUM_COORDS 65536
#define NPTS (BATCH * NUM_COORDS)          // 524288
#define NCELLS (BATCH * VS * VS * VS)      // 8,000,000

#define GROUPS 5
#define GCELLS 512                          // cells per group (2 per thread)
#define CPB (GROUPS * GCELLS)               // 2560 cells per block
#define NBLK (NCELLS / CPB)                 // 3125, exact

// Scratch: zero-initialized at module load; finalize re-zeroes exactly the
// occupied cells it consumes -> graph replays deterministic, no clear pass.
// g_sum ch0..5 = sums(x,y,z,f0,f1,f2), ch6 = count, ch7 = 0.
__device__ float g_sum[(size_t)NCELLS * 8];   // 256 MB
__device__ unsigned char g_flag[NCELLS];      // 8 MB occupancy flags

__global__ void __launch_bounds__(256) scatter_kernel(
    const float* __restrict__ coords,
    const float* __restrict__ feats)
{
    int idx = blockIdx.x * blockDim.x + threadIdx.x;
    if (idx >= NPTS) return;

    float x = coords[idx * 3 + 0];
    float y = coords[idx * 3 + 1];
    float z = coords[idx * 3 + 2];

    // Reference constants collapse in f32: res = denom = 0.01f, shift = -0.01f
    const float shift = 0.01f;
    const float denom = 0.01f;
    int ix = (int)floorf((x + shift) / denom);
    int iy = (int)floorf((y + shift) / denom);
    int iz = (int)floorf((z + shift) / denom);

    if (ix < 1 || ix > VS || iy < 1 || iy > VS || iz < 1 || iz > VS) return;

    int b = idx >> 16;  // NUM_COORDS = 65536
    int cell = ((b * VS + (ix - 1)) * VS + (iy - 1)) * VS + (iz - 1);

    float f0 = feats[idx * 3 + 0];
    float f1 = feats[idx * 3 + 1];
    float f2 = feats[idx * 3 + 2];

    float* s = &g_sum[(size_t)cell * 8];
    // Two v4 return-less reductions per point; count folded into ch6.
    asm volatile("red.global.add.v4.f32 [%0], {%1, %2, %3, %4};"
                 :: "l"(s), "f"(x), "f"(y), "f"(z), "f"(f0) : "memory");
    asm volatile("red.global.add.v4.f32 [%0], {%1, %2, %3, %4};"
                 :: "l"(s + 4), "f"(f1), "f"(f2), "f"(1.0f), "f"(0.0f) : "memory");
    // Benign-race occupancy flag (all writers store 1).
    g_flag[cell] = 1;
}

__global__ void __launch_bounds__(256) finalize_kernel(float* __restrict__ out)
{
    __shared__ __align__(16) float stage[2][GCELLS * 10];  // 2 x 20 KB

    int blockBase = blockIdx.x * CPB;

#pragma unroll
    for (int g = 0; g < GROUPS; g++) {
        int buf = g & 1;
        int gbase = blockBase + g * GCELLS;
        int c0 = gbase + threadIdx.x;        // cell A
        int c1 = c0 + 256;                   // cell B

        // Both flag loads issue together (coalesced, independent).
        unsigned char fA = g_flag[c0];
        unsigned char fB = g_flag[c1];

        // Both predicated float4 pairs issue together -> per-thread MLP=2
        // on the long-latency sparse path.
        float4 aA = make_float4(0.f, 0.f, 0.f, 0.f), bA = aA;
        float4 aB = aA, bB = aA;
        float4* spA = (float4*)&g_sum[(size_t)c0 * 8];
        float4* spB = (float4*)&g_sum[(size_t)c1 * 8];
        if (fA) { aA = spA[0]; bA = spA[1]; }
        if (fB) { aB = spB[0]; bB = spB[1]; }

        // Drain the store issued on this buffer two groups ago before reuse.
        if (g >= 2) {
            if (threadIdx.x == 0) {
                asm volatile("cp.async.bulk.wait_group 1;" ::: "memory");
            }
            __syncthreads();
        }

#pragma unroll
        for (int q = 0; q < 2; q++) {
            int cell = q ? c1 : c0;
            unsigned char flag = q ? fB : fA;
            float4 a = q ? aB : aA;
            float4 b4 = q ? bB : bA;

            // Decode (i, j, k) within the batch's 100^3 block.
            int k = cell % VS;
            int t = cell / VS;
            int j = t % VS;
            int i = (t / VS) % VS;

            float v0 = 0.f, v1 = 0.f, v2 = 0.f, v3 = 0.f, v4 = 0.f, v5 = 0.f;
            float occ = 0.f;
            if (flag) {
                float cnt = b4.z;  // count accumulated in ch6
                v0 = a.x / cnt;
                v1 = a.y / cnt;
                v2 = a.z / cnt;
                v3 = a.w / cnt;
                v4 = b4.x / cnt;
                v5 = b4.y / cnt;
                occ = 1.0f;
                // Self-clean scratch for the next graph replay.
                float4* sp = q ? spB : spA;
                float4 z4 = make_float4(0.f, 0.f, 0.f, 0.f);
                sp[0] = z4;
                sp[1] = z4;
                g_flag[cell] = 0;
            }

            float* st = stage[buf] + (threadIdx.x + q * 256) * 10;
            st[0] = v0;
            st[1] = v1;
            st[2] = v2;
            st[3] = v3;
            st[4] = v4;
            st[5] = v5;
            st[6] = (float)i * 0.01f;
            st[7] = (float)j * 0.01f;
            st[8] = (float)k * 0.01f;
            st[9] = occ;
        }
        __syncthreads();

        if (threadIdx.x == 0) {
            uint32_t smem_addr = (uint32_t)__cvta_generic_to_shared(stage[buf]);
            float* dst = out + (size_t)gbase * 10;
            asm volatile("fence.proxy.async.shared::cta;" ::: "memory");
            asm volatile("cp.async.bulk.global.shared::cta.bulk_group [%0], [%1], %2;"
                         :: "l"(dst), "r"(smem_addr), "r"(GCELLS * 40) : "memory");
            asm volatile("cp.async.bulk.commit_group;" ::: "memory");
        }
    }

    // Keep the CTA (and its smem) alive until all stores drain.
    if (threadIdx.x == 0) {
        asm volatile("cp.async.bulk.wait_group 0;" ::: "memory");
    }
}

extern "C" void kernel_launch(void* const* d_in, const int* in_sizes, int n_in,
                              void* d_out, int out_size)
{
    const float* coords = (const float*)d_in[0];
    const float* feats  = (const float*)d_in[1];
    float* out = (float*)d_out;

    scatter_kernel<<<(NPTS + 255) / 256, 256>>>(coords, feats);
    finalize_kernel<<<NBLK, 256>>>(out);  // 3125 blocks x 2560 cells
}